// round 12
// baseline (speedup 1.0000x reference)
#include <cuda_runtime.h>
#include <cuda_bf16.h>
#include <cstdint>

// ---------------------------------------------------------------------------
// SpikeLinear: out = x @ W^T + bias, then LIF scan (T=16), fully fused.
//
// Round 12: instruction diet on the round-10 structure (4-stage ring, BK=16,
// tot in regs, occ 2, 1437.8 us). W is stored PRE-DUPLICATED in shared as
// u64 {w,w} pairs, eliminating the 4 mov.b64 packs per k-step (~17% of issue
// traffic). k-loop: 4x LDS.128 + 16x FFMA2, nothing else.
//
// We are at ~the FFMA2 rt=3 issue floor (2.72e6 cyc/SMSP; 1340-1430 us over
// the NAT DVFS clock range); this trades ALU issues for smem bandwidth
// (~91 B/cyc/SM < 128 cap).
//
// Arithmetic bitwise-identical to rounds 4-11 (Eigen kc=248 panel
// replication via fma.rn.f32x2, rel_err 0.000970705): ascending-k fmaf per
// panel, folds at k_end = 248/496/744/992/1024, + bias, ascending-t LIF.
// ---------------------------------------------------------------------------

#define KC 248               // Eigen panel width (validated round 4)

#define BM 128
#define BN 64
#define BK 16
#define TN 4
#define T_STEPS 16

#define AS_STAGE_BYTES (BK * BM * 4)                   // 8 KB (fp32)
#define WS_STAGE_BYTES (BK * BN * 8)                   // 8 KB (u64 {w,w})
#define STAGE_BYTES    (AS_STAGE_BYTES + WS_STAGE_BYTES)   // 16 KB
#define SMEM_BYTES     (4 * STAGE_BYTES)               // 64 KB

#define FMA_F32X2(d, a, b, c) \
    asm("fma.rn.f32x2 %0, %1, %2, %3;" : "=l"(d) : "l"(a), "l"(b), "l"(c))
#define ADD_F32X2_(d, a, b) \
    asm("add.rn.f32x2 %0, %1, %2;" : "=l"(d) : "l"(a), "l"(b))
#define PACK_DUP_F32(d, x) \
    asm("mov.b64 %0, {%1, %2};" : "=l"(d) : "f"(x), "f"(x))
#define UNPACK_F32X2_(lo, hi, p) \
    asm("mov.b64 {%0, %1}, %2;" : "=f"(lo), "=f"(hi) : "l"(p))

__global__ __launch_bounds__(256, 2)
void spikelinear_fused_kernel(const float* __restrict__ A,
                              const float* __restrict__ W,
                              const float* __restrict__ bias,
                              float* __restrict__ spikes,
                              int B, int N, int K) {
    extern __shared__ char smem[];
    char* const st0 = smem + 0 * STAGE_BYTES;
    char* const st1 = smem + 1 * STAGE_BYTES;
    char* const st2 = smem + 2 * STAGE_BYTES;
    char* const st3 = smem + 3 * STAGE_BYTES;

    const int tid    = threadIdx.x;          // 0..255
    const int b_tile = blockIdx.y;            // batch tile (8 b's)
    const int bcol   = blockIdx.x;            // N tile

    const int tcol = tid % (BN / TN);          // 0..15
    const int trow = tid / (BN / TN);          // 0..15

    const int b_base = b_tile * (BM / T_STEPS);   // 8 b's per block

    // packed accumulators: [m-pair 0..3][n 0..3]
    unsigned long long cur[4][TN];
    unsigned long long tot[4][TN];
    #pragma unroll
    for (int i = 0; i < 4; i++)
        #pragma unroll
        for (int j = 0; j < TN; j++) { cur[i][j] = 0ull; tot[i][j] = 0ull; }

    const float* Wb = W + (size_t)bcol * BN * K;

    // loader mapping (BK=16): A tile 128x16 -> 2 float4/thread,
    // W tile 64x16 -> 1 float4/thread (stored duplicated as 4x u64).
    const int ld_row = tid / 4;               // 0..63
    const int ld_col = (tid % 4) * 4;         // 0,4,8,12

    // tile_row -> global m: b_local = row>>4, t = row&15, m = t*B + b_base + b_local
    const int tr0 = ld_row;
    const int tr1 = ld_row + 64;
    const float* rowA0 = A + (size_t)((tr0 & 15) * B + b_base + (tr0 >> 4)) * K;
    const float* rowA1 = A + (size_t)((tr1 & 15) * B + b_base + (tr1 >> 4)) * K;
    const float* rowW  = Wb + (size_t)ld_row * K;

    float4 rA0, rA1, rW;

    // STS of the register-held tile into stage S (W duplicated to u64 {w,w})
#define STS_TILE(S)                                                          \
    {                                                                        \
        float* as_ = reinterpret_cast<float*>(S);                            \
        unsigned long long* ws_ =                                            \
            reinterpret_cast<unsigned long long*>((S) + AS_STAGE_BYTES);     \
        as_[(ld_col + 0) * BM + tr0] = rA0.x;                                \
        as_[(ld_col + 1) * BM + tr0] = rA0.y;                                \
        as_[(ld_col + 2) * BM + tr0] = rA0.z;                                \
        as_[(ld_col + 3) * BM + tr0] = rA0.w;                                \
        as_[(ld_col + 0) * BM + tr1] = rA1.x;                                \
        as_[(ld_col + 1) * BM + tr1] = rA1.y;                                \
        as_[(ld_col + 2) * BM + tr1] = rA1.z;                                \
        as_[(ld_col + 3) * BM + tr1] = rA1.w;                                \
        unsigned long long wd_;                                              \
        PACK_DUP_F32(wd_, rW.x); ws_[(ld_col + 0) * BN + ld_row] = wd_;      \
        PACK_DUP_F32(wd_, rW.y); ws_[(ld_col + 1) * BN + ld_row] = wd_;      \
        PACK_DUP_F32(wd_, rW.z); ws_[(ld_col + 2) * BN + ld_row] = wd_;      \
        PACK_DUP_F32(wd_, rW.w); ws_[(ld_col + 3) * BN + ld_row] = wd_;      \
    }

    // one GEMM iteration: prefetch tile I+2, compute stage CUR, STS -> NXT
#define GEMM_ITER(I, CUR, NXT)                                               \
    {                                                                        \
        const int k0_ = (I) * BK;                                            \
        const bool has_pf_ = (I) + 2 < niter;                                \
        if (has_pf_) {                                                       \
            const int kn_ = ((I) + 2) * BK + ld_col;                         \
            rA0 = *reinterpret_cast<const float4*>(rowA0 + kn_);             \
            rA1 = *reinterpret_cast<const float4*>(rowA1 + kn_);             \
            rW  = *reinterpret_cast<const float4*>(rowW + kn_);              \
        }                                                                    \
        int fold_local_ = -1;                                                \
        {                                                                    \
            int next_b_ = ((k0_ / KC) + 1) * KC;                             \
            if (next_b_ <= k0_ + BK)      fold_local_ = next_b_ - k0_ - 1;   \
            else if (k0_ + BK == K)       fold_local_ = BK - 1;              \
        }                                                                    \
        const float* as_ = reinterpret_cast<const float*>(CUR);              \
        const unsigned long long* wd_ =                                      \
            reinterpret_cast<const unsigned long long*>((CUR) +              \
                                                        AS_STAGE_BYTES);     \
        _Pragma("unroll")                                                    \
        for (int k = 0; k < BK; k++) {                                       \
            const ulonglong2* As2_ = reinterpret_cast<const ulonglong2*>(    \
                as_ + k * BM + trow * 8);                                    \
            ulonglong2 al_ = As2_[0];                                        \
            ulonglong2 ah_ = As2_[1];                                        \
            unsigned long long ap_[4] = {al_.x, al_.y, ah_.x, ah_.y};        \
            const ulonglong2* Wd2_ = reinterpret_cast<const ulonglong2*>(    \
                wd_ + k * BN + tcol * 4);                                    \
            ulonglong2 w01_ = Wd2_[0];                                       \
            ulonglong2 w23_ = Wd2_[1];                                       \
            unsigned long long wp_[TN] = {w01_.x, w01_.y, w23_.x, w23_.y};   \
            _Pragma("unroll")                                                \
            for (int i = 0; i < 4; i++)                                      \
                _Pragma("unroll")                                            \
                for (int j = 0; j < TN; j++)                                 \
                    FMA_F32X2(cur[i][j], ap_[i], wp_[j], cur[i][j]);         \
            if (k == fold_local_) {                                          \
                _Pragma("unroll")                                            \
                for (int i = 0; i < 4; i++)                                  \
                    _Pragma("unroll")                                        \
                    for (int j = 0; j < TN; j++) {                           \
                        ADD_F32X2_(tot[i][j], tot[i][j], cur[i][j]);         \
                        cur[i][j] = 0ull;                                    \
                    }                                                        \
            }                                                                \
        }                                                                    \
        if (has_pf_) STS_TILE(NXT);                                          \
    }

    const int niter = K / BK;   // 64

    // ---- prologue: fill stages 0 and 1 ----
    rA0 = *reinterpret_cast<const float4*>(rowA0 + ld_col);
    rA1 = *reinterpret_cast<const float4*>(rowA1 + ld_col);
    rW  = *reinterpret_cast<const float4*>(rowW + ld_col);
    STS_TILE(st0);
    rA0 = *reinterpret_cast<const float4*>(rowA0 + BK + ld_col);
    rA1 = *reinterpret_cast<const float4*>(rowA1 + BK + ld_col);
    rW  = *reinterpret_cast<const float4*>(rowW + BK + ld_col);
    STS_TILE(st1);
    __syncthreads();

    // ---- main loop: 4-stage ring, sync after every odd iteration ----
    for (int i = 0; i < niter; i += 4) {
        GEMM_ITER(i + 0, st0, st2);
        GEMM_ITER(i + 1, st1, st3);
        __syncthreads();
        GEMM_ITER(i + 2, st2, st0);
        GEMM_ITER(i + 3, st3, st1);
        __syncthreads();
    }

    // ------------------------- fused epilogue -------------------------
    // thread rows: tile rows trow*8 + r (r=0..7)
    //   b_local = trow>>1, t = (trow&1)*8 + r
    const int n0 = bcol * BN + tcol * TN;
    const int b  = b_base + (trow >> 1);
    const bool upper = (trow & 1);

    // unpack + bias (identical scalar fp32 add as rounds 4-11)
    float v[8][TN];
    #pragma unroll
    for (int i = 0; i < 4; i++) {
        float lo[TN], hi[TN];
        #pragma unroll
        for (int j = 0; j < TN; j++)
            UNPACK_F32X2_(lo[j], hi[j], tot[i][j]);
        #pragma unroll
        for (int j = 0; j < TN; j++) {
            v[2 * i + 0][j] = lo[j] + bias[n0 + j];
            v[2 * i + 1][j] = hi[j] + bias[n0 + j];
        }
    }

    // LIF scan, ascending t. Pass 1: scan from 0 (valid for lower half).
    float sp[8][TN];
    float fin[TN];
    #pragma unroll
    for (int j = 0; j < TN; j++) {
        float memb = 0.0f;
        #pragma unroll
        for (int r = 0; r < 8; r++) {
            memb += v[r][j];
            float s = (memb > 1.0f) ? 1.0f : 0.0f;
            sp[r][j] = s;
            memb = (s > 0.0f) ? 0.0f : memb;
        }
        fin[j] = memb;
    }
    // hand membrane from lower half (lane l) to upper half (lane l+16)
    #pragma unroll
    for (int j = 0; j < TN; j++)
        fin[j] = __shfl_up_sync(0xffffffffu, fin[j], 16);
    if (upper) {
        #pragma unroll
        for (int j = 0; j < TN; j++) {
            float memb = fin[j];
            #pragma unroll
            for (int r = 0; r < 8; r++) {
                memb += v[r][j];
                float s = (memb > 1.0f) ? 1.0f : 0.0f;
                sp[r][j] = s;
                memb = (s > 0.0f) ? 0.0f : memb;
            }
        }
    }

    // store spikes: row m = t*B + b, t = upper*8 + r
    #pragma unroll
    for (int r = 0; r < 8; r++) {
        const int t = (upper ? 8 : 0) + r;
        float* crow = spikes + (size_t)(t * B + b) * N + n0;
        float4 o;
        o.x = sp[r][0];
        o.y = sp[r][1];
        o.z = sp[r][2];
        o.w = sp[r][3];
        *reinterpret_cast<float4*>(crow) = o;
    }
}

// ----------------------------- launch --------------------------------------
extern "C" void kernel_launch(void* const* d_in, const int* in_sizes, int n_in,
                              void* d_out, int out_size) {
    const float* x    = (const float*)d_in[0];  // [T*B, F_IN]
    const float* w    = (const float*)d_in[1];  // [F_OUT, F_IN]
    const float* bias = (const float*)d_in[2];  // [F_OUT]

    const int F_OUT = in_sizes[2];                 // 1024
    const int F_IN  = in_sizes[1] / F_OUT;         // 1024
    const int M     = in_sizes[0] / F_IN;          // 32768
    const int B     = M / T_STEPS;                 // 2048

    cudaFuncSetAttribute(spikelinear_fused_kernel,
                         cudaFuncAttributeMaxDynamicSharedMemorySize,
                         SMEM_BYTES);

    dim3 grid(F_OUT / BN, B / (BM / T_STEPS));     // (16, 256)
    spikelinear_fused_kernel<<<grid, 256, SMEM_BYTES>>>(x, w, bias,
                                                        (float*)d_out,
                                                        B, F_OUT, F_IN);
}

// round 13
// speedup vs baseline: 1.9106x; 1.9106x over previous
#include <cuda_runtime.h>
#include <cuda_bf16.h>
#include <cstdint>

// ---------------------------------------------------------------------------
// SpikeLinear: out = x @ W^T + bias, then LIF scan (T=16), fully fused.
//
// FINAL (= round 10, measured 1437.8 us, ~95% of the FFMA2 rt=3 issue floor).
//
// Key design decisions, each validated by isolated experiments:
//  - Numerics: bitwise replication of the reference's XLA:CPU/Eigen gebp
//    accumulation (kc=248 panel restart, ascending-k fmaf, ascending panel
//    folds, fp32 bias add, ascending-t LIF scan) -> rel_err 0.000970705.
//    Any reordering (tensor cores, exact fp64 accumulation) FAILS the 1e-3
//    spike-flip threshold (rounds 1-3).
//  - fma.rn.f32x2 (FFMA2): 2 IEEE fp32 FMAs/instr, bit-identical per
//    component; rt=3 (RF banking) => floor ~85 FMA/cyc/SM (round 5).
//  - BK=16, 4-stage smem ring, 1 sync / 2 iters (rounds 8-10 tuned).
//  - LIF fused into epilogue via half-warp shuffle (round 7, -37 us).
//  - W stays fp32 in shared; {w,w} packs on the idle ALU pipe (round 12
//    showed pre-duplicated W saturates the smem crossbar: 2x regression).
// ---------------------------------------------------------------------------

#define KC 248               // Eigen panel width (validated round 4)

#define BM 128
#define BN 64
#define BK 16
#define TN 4
#define T_STEPS 16

#define STAGE_FLOATS (BK * (BM + BN))          // 3072 floats = 12 KB
#define SMEM_BYTES   (4 * STAGE_FLOATS * 4)    // 48 KB

#define FMA_F32X2(d, a, b, c) \
    asm("fma.rn.f32x2 %0, %1, %2, %3;" : "=l"(d) : "l"(a), "l"(b), "l"(c))
#define ADD_F32X2_(d, a, b) \
    asm("add.rn.f32x2 %0, %1, %2;" : "=l"(d) : "l"(a), "l"(b))
#define PACK_DUP_F32(d, x) \
    asm("mov.b64 %0, {%1, %2};" : "=l"(d) : "f"(x), "f"(x))
#define UNPACK_F32X2_(lo, hi, p) \
    asm("mov.b64 {%0, %1}, %2;" : "=f"(lo), "=f"(hi) : "l"(p))

__global__ __launch_bounds__(256, 2)
void spikelinear_fused_kernel(const float* __restrict__ A,
                              const float* __restrict__ W,
                              const float* __restrict__ bias,
                              float* __restrict__ spikes,
                              int B, int N, int K) {
    extern __shared__ float smem[];
    // stage s: As = smem + s*STAGE_FLOATS            ([BK][BM])
    //          Ws = smem + s*STAGE_FLOATS + BK*BM    ([BK][BN])
    float* const st0 = smem + 0 * STAGE_FLOATS;
    float* const st1 = smem + 1 * STAGE_FLOATS;
    float* const st2 = smem + 2 * STAGE_FLOATS;
    float* const st3 = smem + 3 * STAGE_FLOATS;

    const int tid    = threadIdx.x;          // 0..255
    const int b_tile = blockIdx.y;            // batch tile (8 b's)
    const int bcol   = blockIdx.x;            // N tile

    const int tcol = tid % (BN / TN);          // 0..15
    const int trow = tid / (BN / TN);          // 0..15

    const int b_base = b_tile * (BM / T_STEPS);   // 8 b's per block

    // packed accumulators: [m-pair 0..3][n 0..3]
    unsigned long long cur[4][TN];
    unsigned long long tot[4][TN];
    #pragma unroll
    for (int i = 0; i < 4; i++)
        #pragma unroll
        for (int j = 0; j < TN; j++) { cur[i][j] = 0ull; tot[i][j] = 0ull; }

    const float* Wb = W + (size_t)bcol * BN * K;

    // loader mapping (BK=16): A tile 128x16 -> 2 float4/thread,
    // W tile 64x16 -> 1 float4/thread.
    const int ld_row = tid / 4;               // 0..63
    const int ld_col = (tid % 4) * 4;         // 0,4,8,12

    // tile_row -> global m: b_local = row>>4, t = row&15, m = t*B + b_base + b_local
    const int tr0 = ld_row;
    const int tr1 = ld_row + 64;
    const float* rowA0 = A + (size_t)((tr0 & 15) * B + b_base + (tr0 >> 4)) * K;
    const float* rowA1 = A + (size_t)((tr1 & 15) * B + b_base + (tr1 >> 4)) * K;
    const float* rowW  = Wb + (size_t)ld_row * K;

    float4 rA0, rA1, rW;

    // STS of the register-held tile into stage S
#define STS_TILE(S)                                                         \
    {                                                                       \
        float* as_ = (S);                                                   \
        float* ws_ = (S) + BK * BM;                                         \
        as_[(ld_col + 0) * BM + tr0] = rA0.x;                               \
        as_[(ld_col + 1) * BM + tr0] = rA0.y;                               \
        as_[(ld_col + 2) * BM + tr0] = rA0.z;                               \
        as_[(ld_col + 3) * BM + tr0] = rA0.w;                               \
        as_[(ld_col + 0) * BM + tr1] = rA1.x;                               \
        as_[(ld_col + 1) * BM + tr1] = rA1.y;                               \
        as_[(ld_col + 2) * BM + tr1] = rA1.z;                               \
        as_[(ld_col + 3) * BM + tr1] = rA1.w;                               \
        ws_[(ld_col + 0) * BN + ld_row] = rW.x;                             \
        ws_[(ld_col + 1) * BN + ld_row] = rW.y;                             \
        ws_[(ld_col + 2) * BN + ld_row] = rW.z;                             \
        ws_[(ld_col + 3) * BN + ld_row] = rW.w;                             \
    }

    // one GEMM iteration: prefetch tile I+2, compute stage CUR, STS -> NXT
#define GEMM_ITER(I, CUR, NXT)                                              \
    {                                                                       \
        const int k0_ = (I) * BK;                                           \
        const bool has_pf_ = (I) + 2 < niter;                               \
        if (has_pf_) {                                                      \
            const int kn_ = ((I) + 2) * BK + ld_col;                        \
            rA0 = *reinterpret_cast<const float4*>(rowA0 + kn_);            \
            rA1 = *reinterpret_cast<const float4*>(rowA1 + kn_);            \
            rW  = *reinterpret_cast<const float4*>(rowW + kn_);             \
        }                                                                   \
        int fold_local_ = -1;                                               \
        {                                                                   \
            int next_b_ = ((k0_ / KC) + 1) * KC;                            \
            if (next_b_ <= k0_ + BK)      fold_local_ = next_b_ - k0_ - 1;  \
            else if (k0_ + BK == K)       fold_local_ = BK - 1;             \
        }                                                                   \
        const float* as_ = (CUR);                                           \
        const float* ws_ = (CUR) + BK * BM;                                 \
        _Pragma("unroll")                                                   \
        for (int k = 0; k < BK; k++) {                                      \
            const ulonglong2* As2_ = reinterpret_cast<const ulonglong2*>(   \
                as_ + k * BM + trow * 8);                                   \
            ulonglong2 al_ = As2_[0];                                       \
            ulonglong2 ah_ = As2_[1];                                       \
            unsigned long long ap_[4] = {al_.x, al_.y, ah_.x, ah_.y};       \
            const float4* Ws4_ =                                            \
                reinterpret_cast<const float4*>(ws_ + k * BN);              \
            float4 w_ = Ws4_[tcol];                                         \
            unsigned long long wp_[TN];                                     \
            PACK_DUP_F32(wp_[0], w_.x);                                     \
            PACK_DUP_F32(wp_[1], w_.y);                                     \
            PACK_DUP_F32(wp_[2], w_.z);                                     \
            PACK_DUP_F32(wp_[3], w_.w);                                     \
            _Pragma("unroll")                                               \
            for (int i = 0; i < 4; i++)                                     \
                _Pragma("unroll")                                           \
                for (int j = 0; j < TN; j++)                                \
                    FMA_F32X2(cur[i][j], ap_[i], wp_[j], cur[i][j]);        \
            if (k == fold_local_) {                                         \
                _Pragma("unroll")                                           \
                for (int i = 0; i < 4; i++)                                 \
                    _Pragma("unroll")                                       \
                    for (int j = 0; j < TN; j++) {                          \
                        ADD_F32X2_(tot[i][j], tot[i][j], cur[i][j]);        \
                        cur[i][j] = 0ull;                                   \
                    }                                                       \
            }                                                               \
        }                                                                   \
        if (has_pf_) STS_TILE(NXT);                                         \
    }

    const int niter = K / BK;   // 64

    // ---- prologue: fill stages 0 and 1 ----
    rA0 = *reinterpret_cast<const float4*>(rowA0 + ld_col);
    rA1 = *reinterpret_cast<const float4*>(rowA1 + ld_col);
    rW  = *reinterpret_cast<const float4*>(rowW + ld_col);
    STS_TILE(st0);
    rA0 = *reinterpret_cast<const float4*>(rowA0 + BK + ld_col);
    rA1 = *reinterpret_cast<const float4*>(rowA1 + BK + ld_col);
    rW  = *reinterpret_cast<const float4*>(rowW + BK + ld_col);
    STS_TILE(st1);
    __syncthreads();

    // ---- main loop: 4-stage ring, sync after every odd iteration ----
    for (int i = 0; i < niter; i += 4) {
        GEMM_ITER(i + 0, st0, st2);
        GEMM_ITER(i + 1, st1, st3);
        __syncthreads();
        GEMM_ITER(i + 2, st2, st0);
        GEMM_ITER(i + 3, st3, st1);
        __syncthreads();
    }

    // ------------------------- fused epilogue -------------------------
    // thread rows: tile rows trow*8 + r (r=0..7)
    //   b_local = trow>>1, t = (trow&1)*8 + r
    const int n0 = bcol * BN + tcol * TN;
    const int b  = b_base + (trow >> 1);
    const bool upper = (trow & 1);

    // unpack + bias (identical scalar fp32 add as rounds 4-12)
    float v[8][TN];
    #pragma unroll
    for (int i = 0; i < 4; i++) {
        float lo[TN], hi[TN];
        #pragma unroll
        for (int j = 0; j < TN; j++)
            UNPACK_F32X2_(lo[j], hi[j], tot[i][j]);
        #pragma unroll
        for (int j = 0; j < TN; j++) {
            v[2 * i + 0][j] = lo[j] + bias[n0 + j];
            v[2 * i + 1][j] = hi[j] + bias[n0 + j];
        }
    }

    // LIF scan, ascending t. Pass 1: scan from 0 (valid for lower half).
    float sp[8][TN];
    float fin[TN];
    #pragma unroll
    for (int j = 0; j < TN; j++) {
        float memb = 0.0f;
        #pragma unroll
        for (int r = 0; r < 8; r++) {
            memb += v[r][j];
            float s = (memb > 1.0f) ? 1.0f : 0.0f;
            sp[r][j] = s;
            memb = (s > 0.0f) ? 0.0f : memb;
        }
        fin[j] = memb;
    }
    // hand membrane from lower half (lane l) to upper half (lane l+16)
    #pragma unroll
    for (int j = 0; j < TN; j++)
        fin[j] = __shfl_up_sync(0xffffffffu, fin[j], 16);
    if (upper) {
        #pragma unroll
        for (int j = 0; j < TN; j++) {
            float memb = fin[j];
            #pragma unroll
            for (int r = 0; r < 8; r++) {
                memb += v[r][j];
                float s = (memb > 1.0f) ? 1.0f : 0.0f;
                sp[r][j] = s;
                memb = (s > 0.0f) ? 0.0f : memb;
            }
        }
    }

    // store spikes: row m = t*B + b, t = upper*8 + r
    #pragma unroll
    for (int r = 0; r < 8; r++) {
        const int t = (upper ? 8 : 0) + r;
        float* crow = spikes + (size_t)(t * B + b) * N + n0;
        float4 o;
        o.x = sp[r][0];
        o.y = sp[r][1];
        o.z = sp[r][2];
        o.w = sp[r][3];
        *reinterpret_cast<float4*>(crow) = o;
    }
}

// ----------------------------- launch --------------------------------------
extern "C" void kernel_launch(void* const* d_in, const int* in_sizes, int n_in,
                              void* d_out, int out_size) {
    const float* x    = (const float*)d_in[0];  // [T*B, F_IN]
    const float* w    = (const float*)d_in[1];  // [F_OUT, F_IN]
    const float* bias = (const float*)d_in[2];  // [F_OUT]

    const int F_OUT = in_sizes[2];                 // 1024
    const int F_IN  = in_sizes[1] / F_OUT;         // 1024
    const int M     = in_sizes[0] / F_IN;          // 32768
    const int B     = M / T_STEPS;                 // 2048

    cudaFuncSetAttribute(spikelinear_fused_kernel,
                         cudaFuncAttributeMaxDynamicSharedMemorySize,
                         SMEM_BYTES);

    dim3 grid(F_OUT / BN, B / (BM / T_STEPS));     // (16, 256)
    spikelinear_fused_kernel<<<grid, 256, SMEM_BYTES>>>(x, w, bias,
                                                        (float*)d_out,
                                                        B, F_OUT, F_IN);
}